// round 14
// baseline (speedup 1.0000x reference)
#include <cuda_runtime.h>
#include <cuda_fp16.h>
#include <cstdint>
#include <cstddef>

// Problem constants (fixed by the reference setup)
#define BB   2
#define MMT  64
#define NNT  256
#define DDT  256
#define HHT  256
#define ROWS (BB*MMT*NNT)                 // 32768 token rows (b,m,i)

typedef unsigned int u32;
typedef unsigned long long u64;
typedef __half f16;

// ---------------- scratch (device globals; no allocations allowed) ----------
__device__ __align__(16) f16   g_xh[(size_t)ROWS * DDT];            // 16.8 MB LN
__device__ __align__(16) f16   g_LP[(size_t)BB * HHT * MMT * NNT];  // 16.8 MB [b][h][m][i]
__device__ __align__(16) f16   g_RP[(size_t)BB * HHT * MMT * NNT];  // 16.8 MB
__device__ __align__(16) f16   g_oh[(size_t)BB * HHT * NNT * NNT];  // 67 MB [b][h][i][j]
__device__ __align__(16) f16   g_Wh[3][DDT * HHT];                  // W^T [w][n*256+k]
__device__ float g_maskf[ROWS];
__device__ float g_cinv[BB * NNT * NNT];
__device__ int   g_mask_mode;

// ---------------- helpers -----------------------------------------------------
__device__ __forceinline__ u32 smem_u32(const void* p) {
    u32 a;
    asm("{ .reg .u64 t; cvta.to.shared.u64 t, %1; cvt.u32.u64 %0, t; }"
        : "=r"(a) : "l"(p));
    return a;
}

#define CP16(dst, src) \
    asm volatile("cp.async.ca.shared.global [%0], [%1], 16;" :: "r"(dst), "l"(src))
#define CPCOMMIT() asm volatile("cp.async.commit_group;" ::: "memory")
#define CPWAIT(n)  asm volatile("cp.async.wait_group %0;" :: "n"(n) : "memory")

__device__ __forceinline__ void ldsm4(u32 r[4], u32 addr) {
    asm volatile("ldmatrix.sync.aligned.m8n8.x4.shared.b16 {%0,%1,%2,%3}, [%4];"
                 : "=r"(r[0]), "=r"(r[1]), "=r"(r[2]), "=r"(r[3]) : "r"(addr));
}
__device__ __forceinline__ void ldsm4t(u32 r[4], u32 addr) {
    asm volatile("ldmatrix.sync.aligned.m8n8.x4.trans.shared.b16 {%0,%1,%2,%3}, [%4];"
                 : "=r"(r[0]), "=r"(r[1]), "=r"(r[2]), "=r"(r[3]) : "r"(addr));
}

__device__ __forceinline__ void mma_f16(float d[4], const u32 a[4], const u32 b0,
                                        const u32 b1) {
    asm volatile(
        "mma.sync.aligned.m16n8k16.row.col.f32.f16.f16.f32 "
        "{%0,%1,%2,%3}, {%4,%5,%6,%7}, {%8,%9}, {%0,%1,%2,%3};"
        : "+f"(d[0]), "+f"(d[1]), "+f"(d[2]), "+f"(d[3])
        : "r"(a[0]), "r"(a[1]), "r"(a[2]), "r"(a[3]), "r"(b0), "r"(b1));
}

// two fp16 packed
__device__ __forceinline__ u32 pack2h(float a, float b) {
    return (u32)__half_as_ushort(__float2half_rn(a)) |
           ((u32)__half_as_ushort(__float2half_rn(b)) << 16);
}

// ---------------- kernel 0a: detect mask dtype -------------------------------
__global__ void detect_mask_kernel(const u32* p) {
    __shared__ int s_nonbin, s_nonfp;
    if (threadIdx.x == 0) { s_nonbin = 0; s_nonfp = 0; }
    __syncthreads();
    int nonbin = 0, nonfp = 0;
    for (int idx = threadIdx.x; idx < 8192; idx += 256) {
        u32 v = p[idx];
        if (v != 0u && v != 1u)           nonbin = 1;
        if (v != 0u && v != 0x3F800000u)  nonfp  = 1;
    }
    if (nonbin) atomicOr(&s_nonbin, 1);
    if (nonfp)  atomicOr(&s_nonfp, 1);
    __syncthreads();
    if (threadIdx.x == 0) {
        int mode;
        if      (!s_nonbin) mode = 0;
        else if (!s_nonfp)  mode = 1;
        else                mode = 2;
        g_mask_mode = mode;
    }
}

// ---------------- kernel 0b: expand mask to float ----------------------------
__global__ void expand_mask_kernel(const void* p) {
    int r = blockIdx.x * 256 + threadIdx.x;
    int mode = g_mask_mode;
    float f;
    if (mode == 0)      f = (((const int*)p)[r]           != 0)    ? 1.0f : 0.0f;
    else if (mode == 1) f = (((const float*)p)[r]         != 0.0f) ? 1.0f : 0.0f;
    else                f = (((const unsigned char*)p)[r] != 0)    ? 1.0f : 0.0f;
    g_maskf[r] = f;
}

// ---------------- kernel 0c: transpose weights to fp16 -----------------------
__global__ void wsplit_kernel(const float* __restrict__ Wl,
                              const float* __restrict__ Wr,
                              const float* __restrict__ Wo) {
    int idx = blockIdx.x * 256 + threadIdx.x;
    int w = idx >> 16;
    int r = idx & 65535;
    int n = r >> 8, k = r & 255;
    const float* W = (w == 0) ? Wl : ((w == 1) ? Wr : Wo);
    g_Wh[w][n * 256 + k] = __float2half_rn(W[k * 256 + n]);
}

// ---------------- kernel 1: LayerNorm (warp per row) -> fp16 ------------------
__global__ void __launch_bounds__(256) ln_kernel(const float* __restrict__ x,
                                                 const float* __restrict__ w,
                                                 const float* __restrict__ bvec) {
    int lane = threadIdx.x & 31;
    int warp = threadIdx.x >> 5;
    int row  = blockIdx.x * 8 + warp;

    const float4* xr = (const float4*)&x[(size_t)row * DDT];
    float4 v0 = xr[lane * 2];
    float4 v1 = xr[lane * 2 + 1];

    float s  = v0.x + v0.y + v0.z + v0.w + v1.x + v1.y + v1.z + v1.w;
    float sq = v0.x * v0.x + v0.y * v0.y + v0.z * v0.z + v0.w * v0.w +
               v1.x * v1.x + v1.y * v1.y + v1.z * v1.z + v1.w * v1.w;
#pragma unroll
    for (int o = 16; o > 0; o >>= 1) {
        s  += __shfl_xor_sync(0xFFFFFFFFu, s,  o);
        sq += __shfl_xor_sync(0xFFFFFFFFu, sq, o);
    }
    float mu   = s * (1.0f / DDT);
    float var  = sq * (1.0f / DDT) - mu * mu;
    float rstd = rsqrtf(var + 1e-5f);

    const float4* wr = (const float4*)w;
    const float4* br = (const float4*)bvec;
    float4 w0 = wr[lane * 2], w1 = wr[lane * 2 + 1];
    float4 b0 = br[lane * 2], b1 = br[lane * 2 + 1];

    uint4 hv;
    hv.x = pack2h((v0.x - mu) * rstd * w0.x + b0.x,
                  (v0.y - mu) * rstd * w0.y + b0.y);
    hv.y = pack2h((v0.z - mu) * rstd * w0.z + b0.z,
                  (v0.w - mu) * rstd * w0.w + b0.w);
    hv.z = pack2h((v1.x - mu) * rstd * w1.x + b1.x,
                  (v1.y - mu) * rstd * w1.y + b1.y);
    hv.w = pack2h((v1.z - mu) * rstd * w1.z + b1.z,
                  (v1.w - mu) * rstd * w1.w + b1.w);

    *(uint4*)&g_xh[(size_t)row * DDT + lane * 8] = hv;
}

// ---------------- kernel 2: fused L+R projection GEMM ------------------------
// One CTA stages the shared A tile once, computes BOTH projections.
#define RSTRIDE 48
#define PLANE   (128 * RSTRIDE)           // 6144
#define BUFSZ   (3 * PLANE)               // 18432: A, Bl, Br
#define SM_PROJ (2 * BUFSZ)               // 36864 (epilogue reuse: 64*136*2=17408)

__global__ void __launch_bounds__(256) proj_mm(const float* __restrict__ bias_l,
                                               const float* __restrict__ bias_r) {
    __shared__ __align__(16) char sm[SM_PROJ];

    const int tid  = threadIdx.x;
    const int lane = tid & 31;
    const int wid  = tid >> 5;
    const int r0   = blockIdx.y * 128;
    const int n0g  = blockIdx.x * 128;
    const int m0w  = (wid >> 2) * 64;
    const int n0w  = (wid & 3) * 32;

    const f16* Bl16 = g_Wh[0];
    const f16* Br16 = g_Wh[1];

    const u32 smem = smem_u32(sm);
    const int srow = tid >> 1;
    const int sseg = tid & 1;
    const u32 sdst = (u32)(srow * RSTRIDE + sseg * 16);
    const size_t arow = (size_t)(r0 + srow) * 256 + sseg * 8;
    const size_t brow = (size_t)(n0g + srow) * 256 + sseg * 8;

    const u32 aOff = (u32)((lane & 15) * RSTRIDE + (lane >> 4) * 16);
    const u32 bOff = (u32)(((lane & 7) + ((lane >> 4) & 1) * 8) * RSTRIDE +
                           ((lane >> 3) & 1) * 16);

    float accL[4][4][4], accR[4][4][4];
#pragma unroll
    for (int mt = 0; mt < 4; mt++)
#pragma unroll
        for (int nt = 0; nt < 4; nt++)
#pragma unroll
            for (int q = 0; q < 4; q++) { accL[mt][nt][q] = 0.0f; accR[mt][nt][q] = 0.0f; }

    {
        u32 base = smem;
        CP16(base + sdst,             g_xh + arow);
        CP16(base + PLANE + sdst,     Bl16 + brow);
        CP16(base + 2 * PLANE + sdst, Br16 + brow);
        CPCOMMIT();
    }

    for (int c = 0; c < 16; c++) {
        if (c + 1 < 16) {
            u32 base = smem + (u32)(((c + 1) & 1) * BUFSZ);
            size_t koff = (size_t)(c + 1) * 16;
            CP16(base + sdst,             g_xh + arow + koff);
            CP16(base + PLANE + sdst,     Bl16 + brow + koff);
            CP16(base + 2 * PLANE + sdst, Br16 + brow + koff);
            CPCOMMIT();
            CPWAIT(1);
        } else {
            CPWAIT(0);
        }
        __syncthreads();

        const u32 cb = smem + (u32)((c & 1) * BUFSZ);
        u32 bl[8], brv[8];
#pragma unroll
        for (int ntp = 0; ntp < 2; ntp++) {
            u32 ro = (u32)((n0w + ntp * 16) * RSTRIDE) + bOff;
            ldsm4(&bl[ntp * 4],  cb + PLANE + ro);
            ldsm4(&brv[ntp * 4], cb + 2 * PLANE + ro);
        }
#pragma unroll
        for (int mt = 0; mt < 4; mt++) {
            u32 ahi[4];
            ldsm4(ahi, cb + (u32)((m0w + mt * 16) * RSTRIDE) + aOff);
#pragma unroll
            for (int nt = 0; nt < 4; nt++) {
                const u32* b1 = &bl[(nt >> 1) * 4 + (nt & 1) * 2];
                const u32* b2 = &brv[(nt >> 1) * 4 + (nt & 1) * 2];
                mma_f16(accL[mt][nt], ahi, b1[0], b1[1]);
                mma_f16(accR[mt][nt], ahi, b2[0], b2[1]);
            }
        }
        __syncthreads();
    }

    // ---- transposed epilogue: for each of L/R, stage 64h x 128i, write ------
    const int bB = r0 >> 14;
    const int mB = (r0 >> 8) & 63;
    const int i0 = r0 & 255;
    f16* T = (f16*)sm;                    // [64][136] halves
    const int half_mine = n0w >> 6;

    for (int which = 0; which < 2; which++) {
        const float* bias = which ? bias_r : bias_l;
        f16* OutP = which ? g_RP : g_LP;
        float (*acc)[4][4] = which ? accR : accL;

        for (int half = 0; half < 2; half++) {
            __syncthreads();
            if (half_mine == half) {
#pragma unroll
                for (int mt = 0; mt < 4; mt++) {
                    int iA = m0w + mt * 16 + (lane >> 2);
                    int iB = iA + 8;
                    float mfA = g_maskf[r0 + iA];
                    float mfB = g_maskf[r0 + iB];
#pragma unroll
                    for (int nt = 0; nt < 4; nt++) {
                        int nloc = n0w + nt * 8 + (lane & 3) * 2;
                        int hh = nloc - half * 64;
                        float b0 = bias[n0g + nloc], b1 = bias[n0g + nloc + 1];
                        T[hh * 136 + iA]       = __float2half_rn((acc[mt][nt][0] + b0) * mfA);
                        T[(hh + 1) * 136 + iA] = __float2half_rn((acc[mt][nt][1] + b1) * mfA);
                        T[hh * 136 + iB]       = __float2half_rn((acc[mt][nt][2] + b0) * mfB);
                        T[(hh + 1) * 136 + iB] = __float2half_rn((acc[mt][nt][3] + b1) * mfB);
                    }
                }
            }
            __syncthreads();
            int wq = tid >> 5;
#pragma unroll
            for (int rr = 0; rr < 8; rr++) {
                int hh = wq * 8 + rr;
                uint2 v = *(uint2*)&T[hh * 136 + lane * 4];
                int h = n0g + half * 64 + hh;
                *(uint2*)&OutP[(((size_t)(bB * 256 + h)) * 64 + mB) * 256 + i0 + lane * 4] = v;
            }
        }
    }
}

// ---------------- kernel 3: pair-count inverse -------------------------------
__global__ void __launch_bounds__(256) cnt_kernel() {
    int b = blockIdx.x >> 8;
    int i = blockIdx.x & 255;
    int j = threadIdx.x;
    __shared__ float mi[MMT];
    if (j < MMT) mi[j] = g_maskf[(b * MMT + j) * NNT + i];
    __syncthreads();
    float s = 0.0f;
#pragma unroll 8
    for (int m = 0; m < MMT; m++)
        s = fmaf(mi[m], g_maskf[(b * MMT + m) * NNT + j], s);
    g_cinv[((size_t)b * NNT + i) * NNT + j] = 1.0f / ((float)MMT * (s + 1e-5f));
}

// ---------------- kernel 4: outer contraction (single fp16 batched MMA) ------
// Per (b,h): C[i][j] = sum_m L[h][m][i] * R[h][m][j]; full K=64 staged at once.
#define OST  272                           // 128*2B + 16 pad
#define OAB  0
#define OBB  (64 * OST)                    // 17408
#define SM_OUT (2 * 64 * OST)              // 34816

__global__ void __launch_bounds__(256) outer_mm() {
    __shared__ __align__(16) char sm[SM_OUT];

    const int tid  = threadIdx.x;
    const int lane = tid & 31;
    const int wid  = tid >> 5;
    const int h  = blockIdx.x;
    const int i0 = (blockIdx.y >> 1) * 128;
    const int j0 = (blockIdx.y & 1) * 128;
    const int b  = blockIdx.z;
    const int m0w = (wid >> 2) * 64;
    const int n0w = (wid & 3) * 32;

    const f16* gL = g_LP + ((size_t)(b * 256 + h) * 64) * 256 + i0;
    const f16* gR = g_RP + ((size_t)(b * 256 + h) * 64) * 256 + j0;
    const u32 smem = smem_u32(sm);

    float acc[4][4][4];
#pragma unroll
    for (int mt = 0; mt < 4; mt++)
#pragma unroll
        for (int nt = 0; nt < 4; nt++)
#pragma unroll
            for (int q = 0; q < 4; q++) acc[mt][nt][q] = 0.0f;

    const u32 aOffT = (u32)(((lane & 7) + ((lane >> 4) & 1) * 8) * OST +
                            ((lane >> 3) & 1) * 16);
    const u32 bOffT = (u32)(((lane & 7) + ((lane >> 3) & 1) * 8) * OST +
                            ((lane >> 4) & 1) * 16);

    // stage full 64m x 128col tiles for both A and B
#pragma unroll
    for (int q = 0; q < 8; q++) {
        int idx = q * 256 + tid;           // 0..2047
        int arr = idx >> 10;               // 0 = A(L), 1 = B(R)
        int rem = idx & 1023;
        int m   = rem >> 4;
        int pc  = rem & 15;
        const f16* src = (arr ? gR : gL) + (size_t)m * 256 + pc * 8;
        CP16(smem + (u32)(arr * OBB + m * OST + pc * 16), src);
    }
    CPCOMMIT();
    CPWAIT(0);
    __syncthreads();

#pragma unroll
    for (int s = 0; s < 4; s++) {
        const u32 krow = (u32)(s * 16 * OST);
        u32 bhi[8];
#pragma unroll
        for (int ntp = 0; ntp < 2; ntp++) {
            u32 col = (u32)((n0w + ntp * 16) * 2);
            ldsm4t(&bhi[ntp * 4], smem + OBB + krow + col + bOffT);
        }
#pragma unroll
        for (int mt = 0; mt < 4; mt++) {
            u32 ahi[4];
            u32 col = (u32)((m0w + mt * 16) * 2);
            ldsm4t(ahi, smem + OAB + krow + col + aOffT);
#pragma unroll
            for (int nt = 0; nt < 4; nt++) {
                const u32* bh = &bhi[(nt >> 1) * 4 + (nt & 1) * 2];
                mma_f16(acc[mt][nt], ahi, bh[0], bh[1]);
            }
        }
    }

    // epilogue: *cinv, write fp16 plane [b][h][i][j]
    f16* ohB = g_oh + (size_t)(b * 256 + h) * 65536;
#pragma unroll
    for (int mt = 0; mt < 4; mt++) {
        int iA = i0 + m0w + mt * 16 + (lane >> 2);
        int iB = iA + 8;
#pragma unroll
        for (int nt = 0; nt < 4; nt++) {
            int gj = j0 + n0w + nt * 8 + (lane & 3) * 2;
            float c0A = g_cinv[((size_t)b * 256 + iA) * 256 + gj];
            float c1A = g_cinv[((size_t)b * 256 + iA) * 256 + gj + 1];
            float c0B = g_cinv[((size_t)b * 256 + iB) * 256 + gj];
            float c1B = g_cinv[((size_t)b * 256 + iB) * 256 + gj + 1];
            *(u32*)&ohB[(size_t)iA * 256 + gj] =
                pack2h(acc[mt][nt][0] * c0A, acc[mt][nt][1] * c1A);
            *(u32*)&ohB[(size_t)iB * 256 + gj] =
                pack2h(acc[mt][nt][2] * c0B, acc[mt][nt][3] * c1B);
        }
    }
}

// ---------------- kernel 5: final GEMM (single pass over all 256 d-cols) -----
// out[r][d] = sum_h S[b][h][rloc] * Wo^T[d][h] + bo
#define FAST 272
#define FAPL (16 * FAST)          // 4352
#define FBST 48
#define FBPL (256 * FBST)         // 12288 (all 256 d rows)
#define FAH2 0
#define FBH2 FAPL
#define FBUF (FAPL + FBPL)        // 16640

__global__ void __launch_bounds__(256) final_mm(const float* __restrict__ bo,
                                                float* __restrict__ out) {
    __shared__ __align__(16) char sm[2 * FBUF];  // 33280 B

    const int tid  = threadIdx.x;
    const int lane = tid & 31;
    const int wid  = tid >> 5;
    const int r0   = blockIdx.x * 128;
    const int m0w  = (wid >> 2) * 64;
    const int n0w  = (wid & 3) * 64;             // warp covers 64 d-cols
    const int b    = r0 >> 16;
    const int rl0  = r0 & 65535;

    const f16* gAh = g_oh + (size_t)b * 256 * 65536 + rl0;
    const f16* gBh = g_Wh[2];

    const u32 smem = smem_u32(sm);
    const int ahh = tid >> 4, apc = tid & 15;
    const u32 adst = (u32)(ahh * FAST + apc * 16);
    const int srow = tid >> 1, sseg = tid & 1;

    const u32 aOffT = (u32)(((lane & 7) + ((lane >> 4) & 1) * 8) * FAST +
                            ((lane >> 3) & 1) * 16);
    const u32 bOff  = (u32)(((lane & 7) + ((lane >> 4) & 1) * 8) * FBST +
                            ((lane >> 3) & 1) * 16);

    float acc[4][8][4];
#pragma unroll
    for (int mt = 0; mt < 4; mt++)
#pragma unroll
        for (int nt = 0; nt < 8; nt++)
#pragma unroll
            for (int q = 0; q < 4; q++) acc[mt][nt][q] = 0.0f;

    {
        u32 base = smem;
        CP16(base + FAH2 + adst, gAh + (size_t)ahh * 65536 + apc * 8);
#pragma unroll
        for (int t = 0; t < 2; t++) {
            int row = t * 128 + srow;
            CP16(base + FBH2 + (u32)(row * FBST + sseg * 16),
                 gBh + (size_t)row * 256 + sseg * 8);
        }
        CPCOMMIT();
    }

    for (int c = 0; c < 16; c++) {
        if (c + 1 < 16) {
            u32 base = smem + (u32)(((c + 1) & 1) * FBUF);
            size_t hoff = (size_t)(c + 1) * 16;
            CP16(base + FAH2 + adst, gAh + (hoff + ahh) * 65536 + apc * 8);
#pragma unroll
            for (int t = 0; t < 2; t++) {
                int row = t * 128 + srow;
                CP16(base + FBH2 + (u32)(row * FBST + sseg * 16),
                     gBh + (size_t)row * 256 + hoff + sseg * 8);
            }
            CPCOMMIT();
            CPWAIT(1);
        } else {
            CPWAIT(0);
        }
        __syncthreads();

        const u32 cb = smem + (u32)((c & 1) * FBUF);
        u32 bhi[16];
#pragma unroll
        for (int ntp = 0; ntp < 4; ntp++)
            ldsm4(&bhi[ntp * 4], cb + FBH2 + (u32)((n0w + ntp * 16) * FBST) + bOff);
#pragma unroll
        for (int mt = 0; mt < 4; mt++) {
            u32 ahi[4];
            u32 col = (u32)((m0w + mt * 16) * 2);
            ldsm4t(ahi, cb + FAH2 + col + aOffT);
#pragma unroll
            for (int nt = 0; nt < 8; nt++) {
                const u32* bh = &bhi[(nt >> 1) * 4 + (nt & 1) * 2];
                mma_f16(acc[mt][nt], ahi, bh[0], bh[1]);
            }
        }
        __syncthreads();
    }

#pragma unroll
    for (int mt = 0; mt < 4; mt++) {
        size_t rA = (size_t)(r0 + m0w + mt * 16 + (lane >> 2));
        size_t rB = rA + 8;
#pragma unroll
        for (int nt = 0; nt < 8; nt++) {
            int n = n0w + nt * 8 + (lane & 3) * 2;
            float b0 = bo[n], b1 = bo[n + 1];
            float2 v0, v1;
            v0.x = acc[mt][nt][0] + b0;
            v0.y = acc[mt][nt][1] + b1;
            v1.x = acc[mt][nt][2] + b0;
            v1.y = acc[mt][nt][3] + b1;
            *(float2*)&out[rA * 256 + n] = v0;
            *(float2*)&out[rB * 256 + n] = v1;
        }
    }
}

// ---------------- launch ------------------------------------------------------
extern "C" void kernel_launch(void* const* d_in, const int* in_sizes, int n_in,
                              void* d_out, int out_size) {
    // metadata order: x, mask, ln_w, ln_b, Wl, bl, Wr, br, Wo, bo
    const float* x    = (const float*)d_in[0];
    const void*  mask = d_in[1];
    const float* ln_w = (const float*)d_in[2];
    const float* ln_b = (const float*)d_in[3];
    const float* Wl   = (const float*)d_in[4];
    const float* bl   = (const float*)d_in[5];
    const float* Wr   = (const float*)d_in[6];
    const float* br   = (const float*)d_in[7];
    const float* Wo   = (const float*)d_in[8];
    const float* bo   = (const float*)d_in[9];
    float* out = (float*)d_out;

    detect_mask_kernel<<<1, 256>>>((const u32*)mask);
    expand_mask_kernel<<<ROWS / 256, 256>>>(mask);
    wsplit_kernel<<<768, 256>>>(Wl, Wr, Wo);
    ln_kernel<<<ROWS / 8, 256>>>(x, ln_w, ln_b);
    cnt_kernel<<<BB * NNT, 256>>>();
    proj_mm<<<dim3(2, 256), 256>>>(bl, br);
    outer_mm<<<dim3(256, 4, 2), 256>>>();
    final_mm<<<1024, 256>>>(bo, out);
}

// round 15
// speedup vs baseline: 1.1208x; 1.1208x over previous
#include <cuda_runtime.h>
#include <cuda_fp16.h>
#include <cstdint>
#include <cstddef>

// Problem constants (fixed by the reference setup)
#define BB   2
#define MMT  64
#define NNT  256
#define DDT  256
#define HHT  256
#define ROWS (BB*MMT*NNT)                 // 32768 token rows (b,m,i)

typedef unsigned int u32;
typedef unsigned long long u64;
typedef __half f16;

// ---------------- scratch (device globals; no allocations allowed) ----------
__device__ __align__(16) f16   g_xh[(size_t)ROWS * DDT];            // 16.8 MB LN
__device__ __align__(16) f16   g_LP[(size_t)BB * HHT * MMT * NNT];  // 16.8 MB [b][h][m][i]
__device__ __align__(16) f16   g_RP[(size_t)BB * HHT * MMT * NNT];  // 16.8 MB
__device__ __align__(16) f16   g_oh[(size_t)BB * HHT * NNT * NNT];  // 67 MB [b][h][i][j]
__device__ __align__(16) f16   g_Wh[3][DDT * HHT];                  // W^T [w][n*256+k]
__device__ float g_maskf[ROWS];
__device__ float g_cinv[BB * NNT * NNT];
__device__ int   g_mask_mode;

// ---------------- helpers -----------------------------------------------------
__device__ __forceinline__ u32 smem_u32(const void* p) {
    u32 a;
    asm("{ .reg .u64 t; cvta.to.shared.u64 t, %1; cvt.u32.u64 %0, t; }"
        : "=r"(a) : "l"(p));
    return a;
}

#define CP16(dst, src) \
    asm volatile("cp.async.ca.shared.global [%0], [%1], 16;" :: "r"(dst), "l"(src))
#define CPCOMMIT() asm volatile("cp.async.commit_group;" ::: "memory")
#define CPWAIT(n)  asm volatile("cp.async.wait_group %0;" :: "n"(n) : "memory")

__device__ __forceinline__ void ldsm4(u32 r[4], u32 addr) {
    asm volatile("ldmatrix.sync.aligned.m8n8.x4.shared.b16 {%0,%1,%2,%3}, [%4];"
                 : "=r"(r[0]), "=r"(r[1]), "=r"(r[2]), "=r"(r[3]) : "r"(addr));
}
__device__ __forceinline__ void ldsm4t(u32 r[4], u32 addr) {
    asm volatile("ldmatrix.sync.aligned.m8n8.x4.trans.shared.b16 {%0,%1,%2,%3}, [%4];"
                 : "=r"(r[0]), "=r"(r[1]), "=r"(r[2]), "=r"(r[3]) : "r"(addr));
}

__device__ __forceinline__ void mma_f16(float d[4], const u32 a[4], const u32 b0,
                                        const u32 b1) {
    asm volatile(
        "mma.sync.aligned.m16n8k16.row.col.f32.f16.f16.f32 "
        "{%0,%1,%2,%3}, {%4,%5,%6,%7}, {%8,%9}, {%0,%1,%2,%3};"
        : "+f"(d[0]), "+f"(d[1]), "+f"(d[2]), "+f"(d[3])
        : "r"(a[0]), "r"(a[1]), "r"(a[2]), "r"(a[3]), "r"(b0), "r"(b1));
}

// two fp16 packed
__device__ __forceinline__ u32 pack2h(float a, float b) {
    return (u32)__half_as_ushort(__float2half_rn(a)) |
           ((u32)__half_as_ushort(__float2half_rn(b)) << 16);
}

// mask value from the raw buffer (mode resolved by detect kernel)
__device__ __forceinline__ float maskval(const void* p, int mode, int r) {
    if (mode == 0)      return (((const int*)p)[r]           != 0)    ? 1.0f : 0.0f;
    else if (mode == 1) return (((const float*)p)[r]         != 0.0f) ? 1.0f : 0.0f;
    else                return (((const unsigned char*)p)[r] != 0)    ? 1.0f : 0.0f;
}

// ---------------- kernel 0: detect mask dtype --------------------------------
__global__ void detect_mask_kernel(const u32* p) {
    __shared__ int s_nonbin, s_nonfp;
    if (threadIdx.x == 0) { s_nonbin = 0; s_nonfp = 0; }
    __syncthreads();
    int nonbin = 0, nonfp = 0;
    for (int idx = threadIdx.x; idx < 8192; idx += 256) {
        u32 v = p[idx];
        if (v != 0u && v != 1u)           nonbin = 1;
        if (v != 0u && v != 0x3F800000u)  nonfp  = 1;
    }
    if (nonbin) atomicOr(&s_nonbin, 1);
    if (nonfp)  atomicOr(&s_nonfp, 1);
    __syncthreads();
    if (threadIdx.x == 0) {
        int mode;
        if      (!s_nonbin) mode = 0;
        else if (!s_nonfp)  mode = 1;
        else                mode = 2;
        g_mask_mode = mode;
    }
}

// ---------------- kernel 1: merged prep (ln / wsplit / expand / cnt) ---------
// blocks [0,4096): LayerNorm (warp per row) -> g_xh
// blocks [4096,4864): weight transpose -> g_Wh
// blocks [4864,4992): mask expand -> g_maskf
// blocks [4992,5504): pair-count inverse -> g_cinv (reads RAW mask via mode)
__global__ void __launch_bounds__(256) prep_kernel(const float* __restrict__ x,
                                                   const float* __restrict__ w,
                                                   const float* __restrict__ bvec,
                                                   const float* __restrict__ Wl,
                                                   const float* __restrict__ Wr,
                                                   const float* __restrict__ Wo,
                                                   const void* __restrict__ maskraw) {
    const int blk = blockIdx.x;
    const int tid = threadIdx.x;

    if (blk < 4096) {
        // ---- LayerNorm ----
        int lane = tid & 31;
        int warp = tid >> 5;
        int row  = blk * 8 + warp;

        const float4* xr = (const float4*)&x[(size_t)row * DDT];
        float4 v0 = xr[lane * 2];
        float4 v1 = xr[lane * 2 + 1];

        float s  = v0.x + v0.y + v0.z + v0.w + v1.x + v1.y + v1.z + v1.w;
        float sq = v0.x * v0.x + v0.y * v0.y + v0.z * v0.z + v0.w * v0.w +
                   v1.x * v1.x + v1.y * v1.y + v1.z * v1.z + v1.w * v1.w;
#pragma unroll
        for (int o = 16; o > 0; o >>= 1) {
            s  += __shfl_xor_sync(0xFFFFFFFFu, s,  o);
            sq += __shfl_xor_sync(0xFFFFFFFFu, sq, o);
        }
        float mu   = s * (1.0f / DDT);
        float var  = sq * (1.0f / DDT) - mu * mu;
        float rstd = rsqrtf(var + 1e-5f);

        const float4* wr = (const float4*)w;
        const float4* br = (const float4*)bvec;
        float4 w0 = wr[lane * 2], w1 = wr[lane * 2 + 1];
        float4 b0 = br[lane * 2], b1 = br[lane * 2 + 1];

        uint4 hv;
        hv.x = pack2h((v0.x - mu) * rstd * w0.x + b0.x,
                      (v0.y - mu) * rstd * w0.y + b0.y);
        hv.y = pack2h((v0.z - mu) * rstd * w0.z + b0.z,
                      (v0.w - mu) * rstd * w0.w + b0.w);
        hv.z = pack2h((v1.x - mu) * rstd * w1.x + b1.x,
                      (v1.y - mu) * rstd * w1.y + b1.y);
        hv.w = pack2h((v1.z - mu) * rstd * w1.z + b1.z,
                      (v1.w - mu) * rstd * w1.w + b1.w);

        *(uint4*)&g_xh[(size_t)row * DDT + lane * 8] = hv;
    } else if (blk < 4864) {
        // ---- weight transpose + fp16 ----
        int idx = (blk - 4096) * 256 + tid;
        int wsel = idx >> 16;
        int r = idx & 65535;
        int n = r >> 8, k = r & 255;
        const float* W = (wsel == 0) ? Wl : ((wsel == 1) ? Wr : Wo);
        g_Wh[wsel][n * 256 + k] = __float2half_rn(W[k * 256 + n]);
    } else if (blk < 4992) {
        // ---- mask expand ----
        int r = (blk - 4864) * 256 + tid;
        g_maskf[r] = maskval(maskraw, g_mask_mode, r);
    } else {
        // ---- pair-count inverse (reads raw mask; values identical to maskf)
        int blkc = blk - 4992;
        int b = blkc >> 8;
        int i = blkc & 255;
        int j = tid;
        int mode = g_mask_mode;
        __shared__ float mi[MMT];
        if (j < MMT) mi[j] = maskval(maskraw, mode, (b * MMT + j) * NNT + i);
        __syncthreads();
        float s = 0.0f;
#pragma unroll 8
        for (int m = 0; m < MMT; m++)
            s = fmaf(mi[m], maskval(maskraw, mode, (b * MMT + m) * NNT + j), s);
        g_cinv[((size_t)b * NNT + i) * NNT + j] = 1.0f / ((float)MMT * (s + 1e-5f));
    }
}

// ---------------- kernel 2: projection GEMM (single fp16, transposed out) ----
#define RSTRIDE 48
#define PLANE   (128 * RSTRIDE)           // 6144
#define BUFSZ   (2 * PLANE)               // 12288: A at 0, B at PLANE
#define SM_PROJ (2 * BUFSZ)               // 24576 (epilogue reuse: 64*136*2=17408)

__global__ void __launch_bounds__(256) proj_mm(const float* __restrict__ bias_l,
                                               const float* __restrict__ bias_r) {
    __shared__ __align__(16) char sm[SM_PROJ];

    const int tid  = threadIdx.x;
    const int lane = tid & 31;
    const int wid  = tid >> 5;
    const int r0   = blockIdx.y * 128;
    const int n0g  = blockIdx.x * 128;
    const int m0w  = (wid >> 2) * 64;
    const int n0w  = (wid & 3) * 32;

    const f16* Bh; const float* bias; f16* OutP;
    if (blockIdx.z == 0) { Bh = g_Wh[0]; bias = bias_l; OutP = g_LP; }
    else                 { Bh = g_Wh[1]; bias = bias_r; OutP = g_RP; }

    const u32 smem = smem_u32(sm);
    const int srow = tid >> 1;
    const int sseg = tid & 1;
    const u32 sdst = (u32)(srow * RSTRIDE + sseg * 16);
    const size_t arow = (size_t)(r0 + srow) * 256 + sseg * 8;
    const size_t brow = (size_t)(n0g + srow) * 256 + sseg * 8;

    const u32 aOff = (u32)((lane & 15) * RSTRIDE + (lane >> 4) * 16);
    const u32 bOff = (u32)(((lane & 7) + ((lane >> 4) & 1) * 8) * RSTRIDE +
                           ((lane >> 3) & 1) * 16);

    float acc[4][4][4];
#pragma unroll
    for (int mt = 0; mt < 4; mt++)
#pragma unroll
        for (int nt = 0; nt < 4; nt++)
#pragma unroll
            for (int q = 0; q < 4; q++) acc[mt][nt][q] = 0.0f;

    {
        u32 base = smem;
        CP16(base + sdst, g_xh + arow);
        CP16(base + PLANE + sdst, Bh + brow);
        CPCOMMIT();
    }

    for (int c = 0; c < 16; c++) {
        if (c + 1 < 16) {
            u32 base = smem + (u32)(((c + 1) & 1) * BUFSZ);
            size_t koff = (size_t)(c + 1) * 16;
            CP16(base + sdst, g_xh + arow + koff);
            CP16(base + PLANE + sdst, Bh + brow + koff);
            CPCOMMIT();
            CPWAIT(1);
        } else {
            CPWAIT(0);
        }
        __syncthreads();

        const u32 cb = smem + (u32)((c & 1) * BUFSZ);
        u32 bhi[8];
#pragma unroll
        for (int ntp = 0; ntp < 2; ntp++)
            ldsm4(&bhi[ntp * 4], cb + PLANE + (u32)((n0w + ntp * 16) * RSTRIDE) + bOff);
#pragma unroll
        for (int mt = 0; mt < 4; mt++) {
            u32 ahi[4];
            ldsm4(ahi, cb + (u32)((m0w + mt * 16) * RSTRIDE) + aOff);
#pragma unroll
            for (int nt = 0; nt < 4; nt++) {
                const u32* bh = &bhi[(nt >> 1) * 4 + (nt & 1) * 2];
                mma_f16(acc[mt][nt], ahi, bh[0], bh[1]);
            }
        }
        __syncthreads();
    }

    // ---- transposed epilogue: stage 64h x 128i fp16, write [b][h][m][i] -----
    const int bB = r0 >> 14;
    const int mB = (r0 >> 8) & 63;
    const int i0 = r0 & 255;
    f16* T = (f16*)sm;                    // [64][136] halves, 272B row stride
    const int half_mine = n0w >> 6;

    for (int half = 0; half < 2; half++) {
        __syncthreads();
        if (half_mine == half) {
#pragma unroll
            for (int mt = 0; mt < 4; mt++) {
                int iA = m0w + mt * 16 + (lane >> 2);
                int iB = iA + 8;
                float mfA = g_maskf[r0 + iA];
                float mfB = g_maskf[r0 + iB];
#pragma unroll
                for (int nt = 0; nt < 4; nt++) {
                    int nloc = n0w + nt * 8 + (lane & 3) * 2;
                    int hh = nloc - half * 64;
                    float b0 = bias[n0g + nloc], b1 = bias[n0g + nloc + 1];
                    T[hh * 136 + iA]       = __float2half_rn((acc[mt][nt][0] + b0) * mfA);
                    T[(hh + 1) * 136 + iA] = __float2half_rn((acc[mt][nt][1] + b1) * mfA);
                    T[hh * 136 + iB]       = __float2half_rn((acc[mt][nt][2] + b0) * mfB);
                    T[(hh + 1) * 136 + iB] = __float2half_rn((acc[mt][nt][3] + b1) * mfB);
                }
            }
        }
        __syncthreads();
        int wq = tid >> 5;
#pragma unroll
        for (int rr = 0; rr < 8; rr++) {
            int hh = wq * 8 + rr;
            uint2 v = *(uint2*)&T[hh * 136 + lane * 4];
            int h = n0g + half * 64 + hh;
            *(uint2*)&OutP[(((size_t)(bB * 256 + h)) * 64 + mB) * 256 + i0 + lane * 4] = v;
        }
    }
}

// ---------------- kernel 3: outer contraction (single fp16 batched MMA) ------
// Per (b,h): C[i][j] = sum_m L[h][m][i] * R[h][m][j]; full K=64 staged at once.
#define OST  272                           // 128*2B + 16 pad
#define OAB  0
#define OBB  (64 * OST)                    // 17408
#define SM_OUT (2 * 64 * OST)              // 34816

__global__ void __launch_bounds__(256) outer_mm() {
    __shared__ __align__(16) char sm[SM_OUT];

    const int tid  = threadIdx.x;
    const int lane = tid & 31;
    const int wid  = tid >> 5;
    const int h  = blockIdx.x;
    const int i0 = (blockIdx.y >> 1) * 128;
    const int j0 = (blockIdx.y & 1) * 128;
    const int b  = blockIdx.z;
    const int m0w = (wid >> 2) * 64;
    const int n0w = (wid & 3) * 32;

    const f16* gL = g_LP + ((size_t)(b * 256 + h) * 64) * 256 + i0;
    const f16* gR = g_RP + ((size_t)(b * 256 + h) * 64) * 256 + j0;
    const u32 smem = smem_u32(sm);

    float acc[4][4][4];
#pragma unroll
    for (int mt = 0; mt < 4; mt++)
#pragma unroll
        for (int nt = 0; nt < 4; nt++)
#pragma unroll
            for (int q = 0; q < 4; q++) acc[mt][nt][q] = 0.0f;

    const u32 aOffT = (u32)(((lane & 7) + ((lane >> 4) & 1) * 8) * OST +
                            ((lane >> 3) & 1) * 16);
    const u32 bOffT = (u32)(((lane & 7) + ((lane >> 3) & 1) * 8) * OST +
                            ((lane >> 4) & 1) * 16);

    // stage full 64m x 128col tiles for both A and B
#pragma unroll
    for (int q = 0; q < 8; q++) {
        int idx = q * 256 + tid;           // 0..2047
        int arr = idx >> 10;               // 0 = A(L), 1 = B(R)
        int rem = idx & 1023;
        int m   = rem >> 4;
        int pc  = rem & 15;
        const f16* src = (arr ? gR : gL) + (size_t)m * 256 + pc * 8;
        CP16(smem + (u32)(arr * OBB + m * OST + pc * 16), src);
    }
    CPCOMMIT();
    CPWAIT(0);
    __syncthreads();

#pragma unroll
    for (int s = 0; s < 4; s++) {
        const u32 krow = (u32)(s * 16 * OST);
        u32 bhi[8];
#pragma unroll
        for (int ntp = 0; ntp < 2; ntp++) {
            u32 col = (u32)((n0w + ntp * 16) * 2);
            ldsm4t(&bhi[ntp * 4], smem + OBB + krow + col + bOffT);
        }
#pragma unroll
        for (int mt = 0; mt < 4; mt++) {
            u32 ahi[4];
            u32 col = (u32)((m0w + mt * 16) * 2);
            ldsm4t(ahi, smem + OAB + krow + col + aOffT);
#pragma unroll
            for (int nt = 0; nt < 4; nt++) {
                const u32* bh = &bhi[(nt >> 1) * 4 + (nt & 1) * 2];
                mma_f16(acc[mt][nt], ahi, bh[0], bh[1]);
            }
        }
    }

    // epilogue: *cinv, write fp16 plane [b][h][i][j]
    f16* ohB = g_oh + (size_t)(b * 256 + h) * 65536;
#pragma unroll
    for (int mt = 0; mt < 4; mt++) {
        int iA = i0 + m0w + mt * 16 + (lane >> 2);
        int iB = iA + 8;
#pragma unroll
        for (int nt = 0; nt < 4; nt++) {
            int gj = j0 + n0w + nt * 8 + (lane & 3) * 2;
            float c0A = g_cinv[((size_t)b * 256 + iA) * 256 + gj];
            float c1A = g_cinv[((size_t)b * 256 + iA) * 256 + gj + 1];
            float c0B = g_cinv[((size_t)b * 256 + iB) * 256 + gj];
            float c1B = g_cinv[((size_t)b * 256 + iB) * 256 + gj + 1];
            *(u32*)&ohB[(size_t)iA * 256 + gj] =
                pack2h(acc[mt][nt][0] * c0A, acc[mt][nt][1] * c1A);
            *(u32*)&ohB[(size_t)iB * 256 + gj] =
                pack2h(acc[mt][nt][2] * c0B, acc[mt][nt][3] * c1B);
        }
    }
}

// ---------------- kernel 4: final GEMM (single-pass fp16) --------------------
// out[r][d] = sum_h S[b][h][rloc] * Wo^T[d][h] + bo
#define FAST 272
#define FAPL (16 * FAST)          // 4352
#define FBST 48
#define FBPL (128 * FBST)         // 6144
#define FAH2 0
#define FBH2 FAPL
#define FBUF (FAPL + FBPL)        // 10496

__global__ void __launch_bounds__(256) final_mm(const float* __restrict__ bo,
                                                float* __restrict__ out) {
    __shared__ __align__(16) char sm[2 * FBUF];  // 20992 B

    const int tid  = threadIdx.x;
    const int lane = tid & 31;
    const int wid  = tid >> 5;
    const int r0   = blockIdx.y * 128;
    const int n0g  = blockIdx.x * 128;
    const int m0w  = (wid >> 2) * 64;
    const int n0w  = (wid & 3) * 32;
    const int b    = r0 >> 16;
    const int rl0  = r0 & 65535;

    const f16* gAh = g_oh + (size_t)b * 256 * 65536 + rl0;
    const f16* gBh = g_Wh[2];

    const u32 smem = smem_u32(sm);
    const int ahh = tid >> 4, apc = tid & 15;
    const u32 adst = (u32)(ahh * FAST + apc * 16);
    const int srow = tid >> 1, sseg = tid & 1;
    const u32 bdst = (u32)(srow * FBST + sseg * 16);
    const size_t brow = (size_t)(n0g + srow) * 256 + sseg * 8;

    const u32 aOffT = (u32)(((lane & 7) + ((lane >> 4) & 1) * 8) * FAST +
                            ((lane >> 3) & 1) * 16);
    const u32 bOff  = (u32)(((lane & 7) + ((lane >> 4) & 1) * 8) * FBST +
                            ((lane >> 3) & 1) * 16);

    float acc[4][4][4];
#pragma unroll
    for (int mt = 0; mt < 4; mt++)
#pragma unroll
        for (int nt = 0; nt < 4; nt++)
#pragma unroll
            for (int q = 0; q < 4; q++) acc[mt][nt][q] = 0.0f;

    {
        u32 base = smem;
        CP16(base + FAH2 + adst, gAh + (size_t)ahh * 65536 + apc * 8);
        CP16(base + FBH2 + bdst, gBh + brow);
        CPCOMMIT();
    }

    for (int c = 0; c < 16; c++) {
        if (c + 1 < 16) {
            u32 base = smem + (u32)(((c + 1) & 1) * FBUF);
            size_t hoff = (size_t)(c + 1) * 16;
            CP16(base + FAH2 + adst, gAh + (hoff + ahh) * 65536 + apc * 8);
            CP16(base + FBH2 + bdst, gBh + brow + hoff);
            CPCOMMIT();
            CPWAIT(1);
        } else {
            CPWAIT(0);
        }
        __syncthreads();

        const u32 cb = smem + (u32)((c & 1) * FBUF);
        u32 bhi[8];
#pragma unroll
        for (int ntp = 0; ntp < 2; ntp++)
            ldsm4(&bhi[ntp * 4], cb + FBH2 + (u32)((n0w + ntp * 16) * FBST) + bOff);
#pragma unroll
        for (int mt = 0; mt < 4; mt++) {
            u32 ahi[4];
            u32 col = (u32)((m0w + mt * 16) * 2);
            ldsm4t(ahi, cb + FAH2 + col + aOffT);
#pragma unroll
            for (int nt = 0; nt < 4; nt++) {
                const u32* bh = &bhi[(nt >> 1) * 4 + (nt & 1) * 2];
                mma_f16(acc[mt][nt], ahi, bh[0], bh[1]);
            }
        }
        __syncthreads();
    }

#pragma unroll
    for (int mt = 0; mt < 4; mt++) {
        size_t rA = (size_t)(r0 + m0w + mt * 16 + (lane >> 2));
        size_t rB = rA + 8;
#pragma unroll
        for (int nt = 0; nt < 4; nt++) {
            int n = n0g + n0w + nt * 8 + (lane & 3) * 2;
            float b0 = bo[n], b1 = bo[n + 1];
            float2 v0, v1;
            v0.x = acc[mt][nt][0] + b0;
            v0.y = acc[mt][nt][1] + b1;
            v1.x = acc[mt][nt][2] + b0;
            v1.y = acc[mt][nt][3] + b1;
            *(float2*)&out[rA * 256 + n] = v0;
            *(float2*)&out[rB * 256 + n] = v1;
        }
    }
}

// ---------------- launch ------------------------------------------------------
extern "C" void kernel_launch(void* const* d_in, const int* in_sizes, int n_in,
                              void* d_out, int out_size) {
    // metadata order: x, mask, ln_w, ln_b, Wl, bl, Wr, br, Wo, bo
    const float* x    = (const float*)d_in[0];
    const void*  mask = d_in[1];
    const float* ln_w = (const float*)d_in[2];
    const float* ln_b = (const float*)d_in[3];
    const float* Wl   = (const float*)d_in[4];
    const float* bl   = (const float*)d_in[5];
    const float* Wr   = (const float*)d_in[6];
    const float* br   = (const float*)d_in[7];
    const float* Wo   = (const float*)d_in[8];
    const float* bo   = (const float*)d_in[9];
    float* out = (float*)d_out;

    detect_mask_kernel<<<1, 256>>>((const u32*)mask);
    prep_kernel<<<5504, 256>>>(x, ln_w, ln_b, Wl, Wr, Wo, mask);
    proj_mm<<<dim3(2, 256, 2), 256>>>(bl, br);
    outer_mm<<<dim3(256, 4, 2), 256>>>();
    final_mm<<<dim3(2, 1024), 256>>>(bo, out);
}